// round 10
// baseline (speedup 1.0000x reference)
#include <cuda_runtime.h>
#include <cuda_fp16.h>
#include <math_constants.h>

// ---------------------------------------------------------------------------
// VQ-VAE quantize — fp16 HMMA GEMM with register top-2 tracking + exact
// fp32 chain full-scan for ambiguous rows only (~3%).
// If d2 > d1 + MARGIN (MARGIN >= 2*max|d_fast-d_ref|), e1 is provably the
// reference argmin. Ambiguous rows get the round-2-proven exact scan.
// Output (f32): [ z_q_out : 8388608 ][ loss : 1 ][ idx : 32768 ]
// ---------------------------------------------------------------------------

#define N_VEC   32768
#define C_DIM   256
#define N_EMB   1024
#define Z_ELEMS 8388608
#define LOSS_OFF 8388608
#define IDX_OFF  8388609
#define MARGIN  1e-3f

__device__ float  g_e2[N_EMB];
__device__ float  g_rowA[N_VEC];
__device__ int    g_idx[N_VEC];
__device__ double g_loss_part[64];
__device__ float  g_zt[N_VEC * C_DIM];      // z transposed [n][k] fp32
__device__ __half g_zh[N_VEC * C_DIM];      // z transposed [n][k] fp16
__device__ __half g_ch[N_EMB * C_DIM];      // codebook fp16
__device__ float  g_ct[C_DIM * N_EMB];      // codebook transposed fp32 [k][e]
__device__ float  g_d1[N_VEC];
__device__ int    g_e1[N_VEC];
__device__ float  g_d2[N_VEC];
__device__ int    g_worklist[N_VEC];
__device__ int    g_nwork;

// ---------------- helpers ----------------
__device__ __forceinline__ unsigned su32(const void* p) {
    unsigned a;
    asm("{ .reg .u64 t; cvta.to.shared.u64 t, %1; cvt.u32.u64 %0, t; }"
        : "=r"(a) : "l"(p));
    return a;
}
__device__ __forceinline__ void cpa16(unsigned s, const void* g) {
    asm volatile("cp.async.cg.shared.global [%0], [%1], 16;"
                 :: "r"(s), "l"(g) : "memory");
}
#define CPA_COMMIT() asm volatile("cp.async.commit_group;" ::: "memory")
__device__ __forceinline__ void ldm4(unsigned* r, unsigned a) {
    asm volatile("ldmatrix.sync.aligned.m8n8.x4.shared.b16 {%0,%1,%2,%3}, [%4];"
                 : "=r"(r[0]), "=r"(r[1]), "=r"(r[2]), "=r"(r[3]) : "r"(a));
}
__device__ __forceinline__ void mma16816(float* c, const unsigned* a,
                                         const unsigned* b) {
    asm volatile(
        "mma.sync.aligned.m16n8k16.row.col.f32.f16.f16.f32 "
        "{%0,%1,%2,%3}, {%4,%5,%6,%7}, {%8,%9}, {%0,%1,%2,%3};"
        : "+f"(c[0]), "+f"(c[1]), "+f"(c[2]), "+f"(c[3])
        : "r"(a[0]), "r"(a[1]), "r"(a[2]), "r"(a[3]), "r"(b[0]), "r"(b[1]));
}

// ---------------------------------------------------------------------------
// k_prep: exact B_e chains (reference order) + zero loss parts + nwork.
// grid 4x256.
// ---------------------------------------------------------------------------
__global__ void k_prep(const float* __restrict__ cb) {
    int e = blockIdx.x * 256 + threadIdx.x;
    if (e < 64) g_loss_part[e] = 0.0;
    if (e == 0) g_nwork = 0;
    const float* r = cb + e * C_DIM;
    float s = 0.f;
    for (int k = 0; k < C_DIM; ++k) {
        float v = r[k];
        s = __fadd_rn(s, __fmul_rn(v, v));
    }
    g_e2[e] = s;
}

// k_cbhalf: codebook fp32 -> fp16, coalesced. grid 256x256.
__global__ void k_cbhalf(const float* __restrict__ cb) {
    int i = blockIdx.x * 1024 + threadIdx.x;
    #pragma unroll
    for (int q = 0; q < 4; ++q) {
        int j = i + q * 256;
        g_ch[j] = __float2half_rn(cb[j]);
    }
}

// k_cbt: transposed fp32 codebook ct[k][e] for coalesced exact chains.
// grid 256 x 1024 (block = k, thread = e).
__global__ void k_cbt(const float* __restrict__ cb) {
    int k = blockIdx.x, e = threadIdx.x;
    g_ct[k * N_EMB + e] = __ldg(&cb[e * C_DIM + k]);
}

// ---------------------------------------------------------------------------
// k_ztrans: transpose z -> fp16 + fp32 [n][k] + exact A_n chains. grid 512x256.
// ---------------------------------------------------------------------------
__global__ void k_ztrans(const float* __restrict__ z) {
    extern __shared__ float As[];                 // [256][65]
    const int tid = threadIdx.x;
    const int nb  = blockIdx.x;
    const int b   = nb >> 6, h = nb & 63;
    const float* zbase = z + ((long)b << 20) + h * 64;
    {
        const int w = tid & 63, c0 = tid >> 6;
        #pragma unroll 8
        for (int p = 0; p < 64; ++p) {
            int c = c0 + (p << 2);
            As[c * 65 + w] = zbase[(long)c << 12 | w];
        }
    }
    __syncthreads();
    #pragma unroll 4
    for (int w = 0; w < 64; ++w) {
        long row = (long)nb * 64 + w;
        float v = As[tid * 65 + w];
        g_zt[row * 256 + tid] = v;
        g_zh[row * 256 + tid] = __float2half_rn(v);
    }
    if (tid < 64) {
        float s = 0.f;
        for (int c = 0; c < C_DIM; ++c) {
            float v = As[c * 65 + tid];
            s = __fadd_rn(s, __fmul_rn(v, v));
        }
        g_rowA[nb * 64 + tid] = s;
    }
}

// ---------------------------------------------------------------------------
// k_mma: fp16 HMMA distance GEMM + per-thread register top-2 (no epilogue
// barriers/atomics). Block = 64 n-rows, 8 e-tiles of 128 looped, K=256 in
// 64-chunks triple-buffered. 8 warps 2m x 4n, warp tile 32x32.
// smem: A 32KB | B 3x16KB | merge sd1/se1/sd2 3KB = 84992 B.
// ---------------------------------------------------------------------------
#define MB 64
#define SMEM_MMA 84992

__device__ __forceinline__ void loadB(unsigned smB, int cc, int buf, int tid) {
    const int et = cc >> 2, kcw = cc & 3;
    #pragma unroll
    for (int q = 0; q < 4; ++q) {
        int i = q * 256 + tid;
        int n = (i >> 3) & 127, u = i & 7;
        unsigned s = smB + buf * 16384 + n * 128 + ((u ^ (n & 7)) << 4);
        cpa16(s, g_ch + ((long)(et * 128 + n) << 8) + kcw * 64 + u * 8);
    }
}

__global__ void __launch_bounds__(256, 2) k_mma() {
    extern __shared__ char sm[];
    const unsigned sb  = su32(sm);
    const unsigned smA = sb;
    const unsigned smB = sb + 32768;
    float* sd1 = (float*)(sm + 81920);
    int*   se1 = (int*)  (sm + 82944);
    float* sd2 = (float*)(sm + 83968);
    const int tid = threadIdx.x;
    const int n0  = blockIdx.x * MB;

    // prologue: full A (64x256) + B chunks 0,1
    #pragma unroll
    for (int q = 0; q < 8; ++q) {
        int i = q * 256 + tid;
        int kc = i >> 9, n = (i >> 3) & 63, u = i & 7;
        unsigned s = smA + kc * 8192 + n * 128 + ((u ^ (n & 7)) << 4);
        cpa16(s, g_zh + ((long)(n0 + n) << 8) + kc * 64 + u * 8);
    }
    loadB(smB, 0, 0, tid);
    CPA_COMMIT();
    loadB(smB, 1, 1, tid);
    CPA_COMMIT();

    const int lane = tid & 31, wid = tid >> 5;
    const int wm = wid >> 2, wn = wid & 3;
    const int quad = lane >> 2;

    unsigned aoff[2], axor[2], boff[2], bxor[2];
    #pragma unroll
    for (int fm = 0; fm < 2; ++fm) {
        int mr = wm * 32 + fm * 16 + (lane & 15);
        aoff[fm] = mr * 128;
        axor[fm] = (mr & 7) << 4;
    }
    #pragma unroll
    for (int nf = 0; nf < 2; ++nf) {
        int nr = wn * 32 + nf * 16 + (lane & 7) + ((lane >> 4) & 1) * 8;
        boff[nf] = nr * 128;
        bxor[nf] = (nr & 7) << 4;
    }
    const int akhi = (lane >> 4) * 16;
    const int bkhi = ((lane >> 3) & 1) * 16;

    float An[2][2];
    #pragma unroll
    for (int fm = 0; fm < 2; ++fm)
        #pragma unroll
        for (int h = 0; h < 2; ++h)
            An[fm][h] = g_rowA[n0 + wm * 32 + fm * 16 + quad + h * 8];

    // per-thread top-2 per row r = fm*2 + h
    float t1[4], t2[4]; int te[4];
    #pragma unroll
    for (int r = 0; r < 4; ++r) {
        t1[r] = CUDART_INF_F; t2[r] = CUDART_INF_F; te[r] = 0;
    }

    float c[2][4][4];

    for (int cc = 0; cc < 32; ++cc) {
        if (cc >= 30) asm volatile("cp.async.wait_group 0;" ::: "memory");
        else          asm volatile("cp.async.wait_group 1;" ::: "memory");
        __syncthreads();
        if (cc + 2 < 32) {
            loadB(smB, cc + 2, (cc + 2) % 3, tid);
            CPA_COMMIT();
        }
        const int kcw = cc & 3, buf = cc % 3;
        if (kcw == 0) {
            #pragma unroll
            for (int fm = 0; fm < 2; ++fm)
                #pragma unroll
                for (int j = 0; j < 4; ++j)
                    #pragma unroll
                    for (int v = 0; v < 4; ++v) c[fm][j][v] = 0.f;
        }
        const unsigned Abase = smA + kcw * 8192;
        const unsigned Bbase = smB + buf * 16384;
        #pragma unroll
        for (int kk = 0; kk < 4; ++kk) {
            unsigned a[2][4], b[2][4];
            const int kb = kk * 32;
            #pragma unroll
            for (int fm = 0; fm < 2; ++fm)
                ldm4(a[fm], Abase + aoff[fm] + (unsigned)((kb + akhi) ^ axor[fm]));
            #pragma unroll
            for (int nf = 0; nf < 2; ++nf)
                ldm4(b[nf], Bbase + boff[nf] + (unsigned)((kb + bkhi) ^ bxor[nf]));
            #pragma unroll
            for (int fm = 0; fm < 2; ++fm) {
                mma16816(c[fm][0], a[fm], &b[0][0]);
                mma16816(c[fm][1], a[fm], &b[0][2]);
                mma16816(c[fm][2], a[fm], &b[1][0]);
                mma16816(c[fm][3], a[fm], &b[1][2]);
            }
        }
        if (kcw == 3) {
            const int et = cc >> 2;
            const int ebase = et * 128 + wn * 32 + (lane & 3) * 2;
            #pragma unroll
            for (int j = 0; j < 4; ++j) {
                float Be0 = __ldg(&g_e2[ebase + j * 8]);
                float Be1 = __ldg(&g_e2[ebase + j * 8 + 1]);
                #pragma unroll
                for (int fm = 0; fm < 2; ++fm)
                    #pragma unroll
                    for (int v = 0; v < 4; ++v) {
                        int h = v >> 1, r = fm * 2 + h;
                        float Be = (v & 1) ? Be1 : Be0;
                        float d = fmaf(-2.f, c[fm][j][v], An[fm][h] + Be);
                        int e = ebase + j * 8 + (v & 1);
                        if (d < t1[r]) { t2[r] = t1[r]; t1[r] = d; te[r] = e; }
                        else if (d < t2[r]) t2[r] = d;
                    }
            }
        }
    }

    // ---- merge top-2: lanes (e-split within quad-row) then warps (wn) ----
    #pragma unroll
    for (int o = 1; o <= 2; o <<= 1) {
        #pragma unroll
        for (int r = 0; r < 4; ++r) {
            float od1 = __shfl_xor_sync(0xFFFFFFFFu, t1[r], o);
            int   oe  = __shfl_xor_sync(0xFFFFFFFFu, te[r], o);
            float od2 = __shfl_xor_sync(0xFFFFFFFFu, t2[r], o);
            if (od1 < t1[r] || (od1 == t1[r] && oe < te[r])) {
                t2[r] = fminf(t1[r], od2);
                t1[r] = od1; te[r] = oe;
            } else {
                t2[r] = fminf(t2[r], od1);
            }
        }
    }
    if ((lane & 3) == 0) {
        #pragma unroll
        for (int r = 0; r < 4; ++r) {
            int fm = r >> 1, h = r & 1;
            int row = wm * 32 + fm * 16 + h * 8 + quad;
            sd1[row * 4 + wn] = t1[r];
            se1[row * 4 + wn] = te[r];
            sd2[row * 4 + wn] = t2[r];
        }
    }
    __syncthreads();
    if (tid < MB) {
        float d1 = sd1[tid * 4]; int e1 = se1[tid * 4]; float d2 = sd2[tid * 4];
        #pragma unroll
        for (int w = 1; w < 4; ++w) {
            float od1 = sd1[tid * 4 + w];
            int   oe  = se1[tid * 4 + w];
            float od2 = sd2[tid * 4 + w];
            if (od1 < d1 || (od1 == d1 && oe < e1)) {
                d2 = fminf(d1, od2); d1 = od1; e1 = oe;
            } else {
                d2 = fminf(d2, od1);
            }
        }
        g_d1[n0 + tid] = d1;
        g_e1[n0 + tid] = e1;
        g_d2[n0 + tid] = d2;
    }
}

// ---------------------------------------------------------------------------
// k_resolve: gap test. Resolved -> idx + loss; ambiguous -> worklist.
// grid 32 x 1024 (thread per n).
// ---------------------------------------------------------------------------
__global__ void k_resolve(float* __restrict__ out) {
    __shared__ double ws[32];
    const int n = blockIdx.x * 1024 + threadIdx.x;
    const float d1 = g_d1[n], d2 = g_d2[n];
    const int e1 = g_e1[n];
    double l = 0.0;
    if (d2 > d1 + MARGIN) {
        g_idx[n] = e1;
        out[IDX_OFF + n] = (float)e1;
        l = (double)d1;
    } else {
        int w = atomicAdd(&g_nwork, 1);
        g_worklist[w] = n;
    }
    #pragma unroll
    for (int o = 16; o; o >>= 1) l += __shfl_down_sync(0xFFFFFFFFu, l, o);
    const int warp = threadIdx.x >> 5;
    if ((threadIdx.x & 31) == 0) ws[warp] = l;
    __syncthreads();
    if (threadIdx.x < 32) {
        double s = ws[threadIdx.x];
        #pragma unroll
        for (int o = 16; o; o >>= 1) s += __shfl_down_sync(0xFFFFFFFFu, s, o);
        if (threadIdx.x == 0) atomicAdd(&g_loss_part[blockIdx.x], s);
    }
}

// ---------------------------------------------------------------------------
// k_chain: exact full scan for ambiguous rows. Block per work item, grid-
// stride. 256 threads x 4 e-chains each; coalesced via transposed g_ct.
// Each chain = reference-order sequential fmaf (round-2 proven semantics).
// ---------------------------------------------------------------------------
__global__ void k_chain(float* __restrict__ out) {
    __shared__ float zs[256];
    __shared__ float wd[8];
    __shared__ int   we[8];
    const int tid = threadIdx.x, lane = tid & 31, warp = tid >> 5;
    const int nwork = g_nwork;
    for (int w = blockIdx.x; w < nwork; w += gridDim.x) {
        const int n = g_worklist[w];
        __syncthreads();
        zs[tid] = g_zt[(long)n * 256 + tid];
        __syncthreads();
        const float An = g_rowA[n];
        float a0 = 0.f, a1 = 0.f, a2 = 0.f, a3 = 0.f;
        #pragma unroll 8
        for (int k = 0; k < 256; ++k) {
            float zk = zs[k];
            const float* row = g_ct + k * N_EMB + tid;
            a0 = fmaf(zk, __ldg(row),       a0);
            a1 = fmaf(zk, __ldg(row + 256), a1);
            a2 = fmaf(zk, __ldg(row + 512), a2);
            a3 = fmaf(zk, __ldg(row + 768), a3);
        }
        float bd = CUDART_INF_F; int bi = 0x7fffffff;
        float acc[4] = {a0, a1, a2, a3};
        #pragma unroll
        for (int q = 0; q < 4; ++q) {
            int e = tid + q * 256;
            float d = __fsub_rn(__fadd_rn(An, g_e2[e]),
                                __fmul_rn(2.0f, acc[q]));
            if (d < bd || (d == bd && e < bi)) { bd = d; bi = e; }
        }
        #pragma unroll
        for (int o = 16; o; o >>= 1) {
            float od = __shfl_xor_sync(0xFFFFFFFFu, bd, o);
            int   oi = __shfl_xor_sync(0xFFFFFFFFu, bi, o);
            if (od < bd || (od == bd && oi < bi)) { bd = od; bi = oi; }
        }
        if (lane == 0) { wd[warp] = bd; we[warp] = bi; }
        __syncthreads();
        if (tid == 0) {
            float fd = wd[0]; int fe = we[0];
            #pragma unroll
            for (int q = 1; q < 8; ++q) {
                if (wd[q] < fd || (wd[q] == fd && we[q] < fe)) {
                    fd = wd[q]; fe = we[q];
                }
            }
            g_idx[n] = fe;
            out[IDX_OFF + n] = (float)fe;
            atomicAdd(&g_loss_part[n & 63], (double)fd);
        }
    }
}

// ---------------------------------------------------------------------------
// k_scatter: grid 1024 (block = (b,h) x c-half), float4 writes.
// ---------------------------------------------------------------------------
#define SC_SM_FLOATS (128 * 68 + 64)
__global__ void k_scatter(const float* __restrict__ cb,
                          float* __restrict__ out)
{
    extern __shared__ float ss[];
    float* srow = ss;                         // [128][68]
    int*   sidx = (int*)(ss + 128 * 68);

    const int tid = threadIdx.x;
    const int nb = blockIdx.x >> 1, chalf = blockIdx.x & 1;
    if (tid < 64) sidx[tid] = g_idx[nb * 64 + tid];
    __syncthreads();

    #pragma unroll 8
    for (int it = 0; it < 32; ++it) {
        int i = it * 256 + tid;
        int w = i >> 7, cloc = i & 127;
        srow[cloc * 68 + w] = __ldg(&cb[sidx[w] * C_DIM + chalf * 128 + cloc]);
    }
    __syncthreads();

    const int b = nb >> 6, h = nb & 63;
    const int w4 = (tid & 15) << 2;
    float* base = out + ((long)b << 20) + ((long)chalf << 19) + (h << 6);
    #pragma unroll
    for (int p = 0; p < 8; ++p) {
        int cloc = (tid >> 4) + p * 16;
        *(float4*)&base[((long)cloc << 12) + w4] =
            *(float4*)&srow[cloc * 68 + w4];
    }
}

__global__ void k_loss(float* __restrict__ out) {
    double s = 0.0;
    #pragma unroll
    for (int i = 0; i < 64; ++i) s += g_loss_part[i];
    out[LOSS_OFF] = (float)(1.25 * s / (double)Z_ELEMS);
}

// ---------------------------------------------------------------------------
extern "C" void kernel_launch(void* const* d_in, const int* in_sizes, int n_in,
                              void* d_out, int out_size) {
    const float* z  = (const float*)d_in[0];
    const float* cb = (const float*)d_in[1];
    if (n_in >= 2 && in_sizes[0] == N_EMB * C_DIM && in_sizes[1] == Z_ELEMS) {
        z  = (const float*)d_in[1];
        cb = (const float*)d_in[0];
    }
    float* out = (float*)d_out;

    cudaFuncSetAttribute(k_ztrans, cudaFuncAttributeMaxDynamicSharedMemorySize,
                         256 * 65 * 4);
    cudaFuncSetAttribute(k_mma, cudaFuncAttributeMaxDynamicSharedMemorySize,
                         SMEM_MMA);
    cudaFuncSetAttribute(k_scatter, cudaFuncAttributeMaxDynamicSharedMemorySize,
                         SC_SM_FLOATS * 4);

    k_prep<<<4, 256>>>(cb);
    k_cbhalf<<<256, 256>>>(cb);
    k_cbt<<<256, 1024>>>(cb);
    k_ztrans<<<512, 256, 256 * 65 * 4>>>(z);
    k_mma<<<512, 256, SMEM_MMA>>>();
    k_resolve<<<32, 1024>>>(out);
    k_chain<<<1024, 256>>>(out);
    k_scatter<<<1024, 256, SC_SM_FLOATS * 4>>>(cb, out);
    k_loss<<<1, 1>>>(out);
}

// round 11
// speedup vs baseline: 2.2263x; 2.2263x over previous
#include <cuda_runtime.h>
#include <cuda_fp16.h>
#include <math_constants.h>

// ---------------------------------------------------------------------------
// VQ-VAE quantize — fp16 HMMA (mma.sync) candidate GEMM + exact fp32
// sequential-chain rescoring. EXACT round-5 build (measured 225.3 us) with
// ONE substitution: float4-write k_scatter (measured 32 -> ~18 us).
// Output (f32): [ z_q_out : 8388608 ][ loss : 1 ][ idx : 32768 ]
// ---------------------------------------------------------------------------

#define N_VEC   32768
#define C_DIM   256
#define N_EMB   1024
#define Z_ELEMS 8388608
#define LOSS_OFF 8388608
#define IDX_OFF  8388609
#define MARGIN  1e-3f
#define CAP     24

__device__ float  g_e2[N_EMB];
__device__ float  g_rowA[N_VEC];
__device__ int    g_idx[N_VEC];
__device__ double g_loss_sum;
__device__ __half g_zh[N_VEC * C_DIM];      // z transposed [n][k] fp16
__device__ __half g_ch[N_EMB * C_DIM];      // codebook fp16
__device__ unsigned short g_cand[N_VEC * CAP];
__device__ float  g_candd[N_VEC * CAP];
__device__ int    g_cnt[N_VEC];
__device__ float  g_bestd[N_VEC];

// ---------------- helpers ----------------
__device__ __forceinline__ unsigned su32(const void* p) {
    unsigned a;
    asm("{ .reg .u64 t; cvta.to.shared.u64 t, %1; cvt.u32.u64 %0, t; }"
        : "=r"(a) : "l"(p));
    return a;
}
__device__ __forceinline__ void cpa16(unsigned s, const void* g) {
    asm volatile("cp.async.cg.shared.global [%0], [%1], 16;"
                 :: "r"(s), "l"(g) : "memory");
}
#define CPA_COMMIT() asm volatile("cp.async.commit_group;" ::: "memory")
__device__ __forceinline__ void ldm4(unsigned* r, unsigned a) {
    asm volatile("ldmatrix.sync.aligned.m8n8.x4.shared.b16 {%0,%1,%2,%3}, [%4];"
                 : "=r"(r[0]), "=r"(r[1]), "=r"(r[2]), "=r"(r[3]) : "r"(a));
}
__device__ __forceinline__ void mma16816(float* c, const unsigned* a,
                                         const unsigned* b) {
    asm volatile(
        "mma.sync.aligned.m16n8k16.row.col.f32.f16.f16.f32 "
        "{%0,%1,%2,%3}, {%4,%5,%6,%7}, {%8,%9}, {%0,%1,%2,%3};"
        : "+f"(c[0]), "+f"(c[1]), "+f"(c[2]), "+f"(c[3])
        : "r"(a[0]), "r"(a[1]), "r"(a[2]), "r"(a[3]), "r"(b[0]), "r"(b[1]));
}
__device__ __forceinline__ unsigned fkey(float f) {
    unsigned b = __float_as_uint(f);
    return (b & 0x80000000u) ? ~b : (b | 0x80000000u);
}
__device__ __forceinline__ float funkey(unsigned k) {
    unsigned b = (k & 0x80000000u) ? (k & 0x7fffffffu) : ~k;
    return __uint_as_float(b);
}

// ---------------------------------------------------------------------------
// k_prep: exact B_e chains (reference order) + zero loss accum. grid 4x256.
// ---------------------------------------------------------------------------
__global__ void k_prep(const float* __restrict__ cb) {
    int e = blockIdx.x * 256 + threadIdx.x;
    if (e == 0) g_loss_sum = 0.0;
    const float* r = cb + e * C_DIM;
    float s = 0.f;
    for (int k = 0; k < C_DIM; ++k) {
        float v = r[k];
        s = __fadd_rn(s, __fmul_rn(v, v));
    }
    g_e2[e] = s;
}

// k_cbhalf: codebook fp32 -> fp16, coalesced. grid 256x256.
__global__ void k_cbhalf(const float* __restrict__ cb) {
    int i = blockIdx.x * 1024 + threadIdx.x;
    #pragma unroll
    for (int q = 0; q < 4; ++q) {
        int j = i + q * 256;
        g_ch[j] = __float2half_rn(cb[j]);
    }
}

// ---------------------------------------------------------------------------
// k_ztrans: transpose z -> fp16 [n][k] + exact A_n chains. grid 512x256.
// ---------------------------------------------------------------------------
__global__ void k_ztrans(const float* __restrict__ z) {
    extern __shared__ float As[];                 // [256][65]
    const int tid = threadIdx.x;
    const int nb  = blockIdx.x;                   // (b,h)
    const int b   = nb >> 6, h = nb & 63;
    const float* zbase = z + ((long)b << 20) + h * 64;
    {
        const int w = tid & 63, c0 = tid >> 6;
        #pragma unroll 8
        for (int p = 0; p < 64; ++p) {
            int c = c0 + (p << 2);
            As[c * 65 + w] = zbase[(long)c << 12 | w];
        }
    }
    __syncthreads();
    #pragma unroll 4
    for (int w = 0; w < 64; ++w) {
        long row = (long)nb * 64 + w;
        g_zh[row * 256 + tid] = __float2half_rn(As[tid * 65 + w]);
    }
    if (tid < 64) {
        float s = 0.f;
        for (int c = 0; c < C_DIM; ++c) {
            float v = As[c * 65 + tid];
            s = __fadd_rn(s, __fmul_rn(v, v));
        }
        g_rowA[nb * 64 + tid] = s;
    }
}

// ---------------------------------------------------------------------------
// k_mma: fp16 HMMA distance GEMM + fused running-min + candidate collection.
// Block: 64 n-rows x (8 e-tiles of 128, looped) x K=256 (cp.async 64-chunks,
// triple-buffered). 8 warps as 2(M) x 4(N); warp tile 32x32.
// smem: A 4*8KB | B 3*16KB | keys 64 u32 | cnt 64 s32  = 82432 B.
// ---------------------------------------------------------------------------
#define MB 64
#define SMEM_MMA 82432

__device__ __forceinline__ void loadB(unsigned smB, int cc, int buf, int tid) {
    const int et = cc >> 2, kcw = cc & 3;
    #pragma unroll
    for (int q = 0; q < 4; ++q) {
        int i = q * 256 + tid;
        int n = (i >> 3) & 127, u = i & 7;
        unsigned s = smB + buf * 16384 + n * 128 + ((u ^ (n & 7)) << 4);
        cpa16(s, g_ch + ((long)(et * 128 + n) << 8) + kcw * 64 + u * 8);
    }
}

__global__ void __launch_bounds__(256, 2) k_mma() {
    extern __shared__ char sm[];
    const unsigned sb  = su32(sm);
    const unsigned smA = sb;
    const unsigned smB = sb + 32768;
    unsigned* skey = (unsigned*)(sm + 81920);
    int*      scnt = (int*)(sm + 82176);
    const int tid = threadIdx.x;
    const int n0  = blockIdx.x * MB;

    if (tid < MB) { skey[tid] = 0xFFFFFFFFu; scnt[tid] = 0; }

    // prologue: A (all 64x256) + B chunk0 as group0, B chunk1 as group1
    #pragma unroll
    for (int q = 0; q < 8; ++q) {
        int i = q * 256 + tid;
        int kc = i >> 9, n = (i >> 3) & 63, u = i & 7;
        unsigned s = smA + kc * 8192 + n * 128 + ((u ^ (n & 7)) << 4);
        cpa16(s, g_zh + ((long)(n0 + n) << 8) + kc * 64 + u * 8);
    }
    loadB(smB, 0, 0, tid);
    CPA_COMMIT();
    loadB(smB, 1, 1, tid);
    CPA_COMMIT();

    const int lane = tid & 31, wid = tid >> 5;
    const int wm = wid >> 2, wn = wid & 3;         // 2m x 4n warps
    const int quad = lane >> 2;

    unsigned aoff[2], axor[2], boff[2], bxor[2];
    #pragma unroll
    for (int fm = 0; fm < 2; ++fm) {
        int mr = wm * 32 + fm * 16 + (lane & 15);
        aoff[fm] = mr * 128;
        axor[fm] = (mr & 7) << 4;
    }
    #pragma unroll
    for (int nf = 0; nf < 2; ++nf) {
        int nr = wn * 32 + nf * 16 + (lane & 7) + ((lane >> 4) & 1) * 8;
        boff[nf] = nr * 128;
        bxor[nf] = (nr & 7) << 4;
    }
    const int akhi = (lane >> 4) * 16;
    const int bkhi = ((lane >> 3) & 1) * 16;

    float An[2][2];
    #pragma unroll
    for (int fm = 0; fm < 2; ++fm)
        #pragma unroll
        for (int h = 0; h < 2; ++h)
            An[fm][h] = g_rowA[n0 + wm * 32 + fm * 16 + quad + h * 8];

    float c[2][4][4];

    for (int cc = 0; cc < 32; ++cc) {
        if (cc >= 30) asm volatile("cp.async.wait_group 0;" ::: "memory");
        else          asm volatile("cp.async.wait_group 1;" ::: "memory");
        __syncthreads();
        if (cc + 2 < 32) {
            loadB(smB, cc + 2, (cc + 2) % 3, tid);
            CPA_COMMIT();
        }
        const int kcw = cc & 3, buf = cc % 3;
        if (kcw == 0) {
            #pragma unroll
            for (int fm = 0; fm < 2; ++fm)
                #pragma unroll
                for (int j = 0; j < 4; ++j)
                    #pragma unroll
                    for (int v = 0; v < 4; ++v) c[fm][j][v] = 0.f;
        }
        const unsigned Abase = smA + kcw * 8192;
        const unsigned Bbase = smB + buf * 16384;
        #pragma unroll
        for (int kk = 0; kk < 4; ++kk) {
            unsigned a[2][4], b[2][4];
            const int kb = kk * 32;
            #pragma unroll
            for (int fm = 0; fm < 2; ++fm)
                ldm4(a[fm], Abase + aoff[fm] + (unsigned)((kb + akhi) ^ axor[fm]));
            #pragma unroll
            for (int nf = 0; nf < 2; ++nf)
                ldm4(b[nf], Bbase + boff[nf] + (unsigned)((kb + bkhi) ^ bxor[nf]));
            #pragma unroll
            for (int fm = 0; fm < 2; ++fm) {
                mma16816(c[fm][0], a[fm], &b[0][0]);
                mma16816(c[fm][1], a[fm], &b[0][2]);
                mma16816(c[fm][2], a[fm], &b[1][0]);
                mma16816(c[fm][3], a[fm], &b[1][2]);
            }
        }
        if (kcw == 3) {
            const int et = cc >> 2;
            // pass 1: d values + per-row running min
            float Be[4][2];
            #pragma unroll
            for (int j = 0; j < 4; ++j) {
                int e0c = et * 128 + wn * 32 + j * 8 + (lane & 3) * 2;
                Be[j][0] = g_e2[e0c];
                Be[j][1] = g_e2[e0c + 1];
            }
            float dmin[2][2] = {{CUDART_INF_F, CUDART_INF_F},
                                {CUDART_INF_F, CUDART_INF_F}};
            #pragma unroll
            for (int fm = 0; fm < 2; ++fm)
                #pragma unroll
                for (int j = 0; j < 4; ++j)
                    #pragma unroll
                    for (int v = 0; v < 4; ++v) {
                        int h = v >> 1;
                        float d = fmaf(-2.f, c[fm][j][v], An[fm][h] + Be[j][v & 1]);
                        c[fm][j][v] = d;
                        dmin[fm][h] = fminf(dmin[fm][h], d);
                    }
            #pragma unroll
            for (int fm = 0; fm < 2; ++fm)
                #pragma unroll
                for (int h = 0; h < 2; ++h) {
                    float m = dmin[fm][h];
                    m = fminf(m, __shfl_xor_sync(0xFFFFFFFFu, m, 1));
                    m = fminf(m, __shfl_xor_sync(0xFFFFFFFFu, m, 2));
                    if ((lane & 3) == 0)
                        atomicMin(&skey[wm * 32 + fm * 16 + quad + h * 8], fkey(m));
                }
            __syncthreads();
            // pass 2: append candidates vs (prefix) min + margin
            #pragma unroll
            for (int fm = 0; fm < 2; ++fm)
                #pragma unroll
                for (int j = 0; j < 4; ++j)
                    #pragma unroll
                    for (int v = 0; v < 4; ++v) {
                        int h = v >> 1;
                        int rloc = wm * 32 + fm * 16 + quad + h * 8;
                        float d = c[fm][j][v];
                        if (d <= funkey(skey[rloc]) + MARGIN) {
                            int slot = atomicAdd(&scnt[rloc], 1);
                            if (slot < CAP) {
                                int e = et * 128 + wn * 32 + j * 8
                                      + (lane & 3) * 2 + (v & 1);
                                g_cand[(long)(n0 + rloc) * CAP + slot] =
                                    (unsigned short)e;
                                g_candd[(long)(n0 + rloc) * CAP + slot] = d;
                            }
                        }
                    }
        }
    }
    __syncthreads();
    if (tid < MB) {
        g_bestd[n0 + tid] = funkey(skey[tid]);
        g_cnt[n0 + tid]   = scnt[tid];
    }
}

// ---------------------------------------------------------------------------
// k_rescore: filter candidates vs final min+margin. Unique survivor -> done
// (provably exact). Else exact sequential-fmaf chains, lex (d,e) min.
// grid 4096 x 256 (warp per n).
// ---------------------------------------------------------------------------
__device__ __forceinline__ float chainM(const float* __restrict__ zb,
                                        const float* __restrict__ cr) {
    float s = 0.f;
    #pragma unroll 8
    for (int k = 0; k < C_DIM; ++k)
        s = fmaf(__ldg(zb + ((long)k << 12)), __ldg(cr + k), s);
    return s;
}

__global__ void k_rescore(const float* __restrict__ z,
                          const float* __restrict__ cb,
                          float* __restrict__ out) {
    __shared__ double lsum[8];
    const int warp = threadIdx.x >> 5, lid = threadIdx.x & 31;
    const int n = blockIdx.x * 8 + warp;
    const int cnt = g_cnt[n];
    const float bmin = g_bestd[n];
    const float An = g_rowA[n];
    const float* zb = z + ((long)(n >> 12) << 20) + (n & 4095);

    float bd = CUDART_INF_F;
    int   bi = 0x7fffffff;

    if (cnt <= CAP) {
        float df = CUDART_INF_F;
        int   e  = 0x7fffffff;
        bool act = false;
        if (lid < cnt) {
            df = g_candd[(long)n * CAP + lid];
            e  = g_cand[(long)n * CAP + lid];
            act = (df <= bmin + MARGIN);
        }
        unsigned bal = __ballot_sync(0xFFFFFFFFu, act);
        if (__popc(bal) == 1) {
            if (act) { bd = df; bi = e; }       // provably the exact argmin
        } else if (act) {
            float M = chainM(zb, cb + (long)e * C_DIM);
            bd = __fsub_rn(__fadd_rn(An, g_e2[e]), __fmul_rn(2.0f, M));
            bi = e;
        }
    } else {
        for (int base = 0; base < N_EMB; base += 32) {
            int e = base + lid;
            float M = chainM(zb, cb + (long)e * C_DIM);
            float d = __fsub_rn(__fadd_rn(An, g_e2[e]), __fmul_rn(2.0f, M));
            if (d < bd || (d == bd && e < bi)) { bd = d; bi = e; }
        }
    }
    #pragma unroll
    for (int o = 16; o; o >>= 1) {
        float od = __shfl_xor_sync(0xFFFFFFFFu, bd, o);
        int   oi = __shfl_xor_sync(0xFFFFFFFFu, bi, o);
        if (od < bd || (od == bd && oi < bi)) { bd = od; bi = oi; }
    }
    if (lid == 0) {
        g_idx[n] = bi;
        out[IDX_OFF + n] = (float)bi;
        lsum[warp] = (double)bd;
    }
    __syncthreads();
    if (threadIdx.x == 0) {
        double s = 0.0;
        #pragma unroll
        for (int w = 0; w < 8; ++w) s += lsum[w];
        atomicAdd(&g_loss_sum, s);
    }
}

// ---------------------------------------------------------------------------
// k_scatter: grid 1024 (block = (b,h) x c-half), float4 writes.
// smem srow[128][68] (float4-aligned rows) + sidx[64] = 35072 B.
// ---------------------------------------------------------------------------
#define SC_SM_FLOATS (128 * 68 + 64)
__global__ void k_scatter(const float* __restrict__ cb,
                          float* __restrict__ out)
{
    extern __shared__ float ss[];
    float* srow = ss;                         // [128][68]
    int*   sidx = (int*)(ss + 128 * 68);

    const int tid = threadIdx.x;
    const int nb = blockIdx.x >> 1, chalf = blockIdx.x & 1;
    if (tid < 64) sidx[tid] = g_idx[nb * 64 + tid];
    __syncthreads();

    #pragma unroll 8
    for (int it = 0; it < 32; ++it) {
        int i = it * 256 + tid;
        int w = i >> 7, cloc = i & 127;
        srow[cloc * 68 + w] = __ldg(&cb[sidx[w] * C_DIM + chalf * 128 + cloc]);
    }
    __syncthreads();

    const int b = nb >> 6, h = nb & 63;
    const int w4 = (tid & 15) << 2;
    float* base = out + ((long)b << 20) + ((long)chalf << 19) + (h << 6);
    #pragma unroll
    for (int p = 0; p < 8; ++p) {
        int cloc = (tid >> 4) + p * 16;
        *(float4*)&base[((long)cloc << 12) + w4] =
            *(float4*)&srow[cloc * 68 + w4];
    }
}

__global__ void k_loss(float* __restrict__ out) {
    out[LOSS_OFF] = (float)(1.25 * g_loss_sum / (double)Z_ELEMS);
}

// ---------------------------------------------------------------------------
extern "C" void kernel_launch(void* const* d_in, const int* in_sizes, int n_in,
                              void* d_out, int out_size) {
    const float* z  = (const float*)d_in[0];
    const float* cb = (const float*)d_in[1];
    if (n_in >= 2 && in_sizes[0] == N_EMB * C_DIM && in_sizes[1] == Z_ELEMS) {
        z  = (const float*)d_in[1];
        cb = (const float*)d_in[0];
    }
    float* out = (float*)d_out;

    cudaFuncSetAttribute(k_ztrans, cudaFuncAttributeMaxDynamicSharedMemorySize,
                         256 * 65 * 4);
    cudaFuncSetAttribute(k_mma, cudaFuncAttributeMaxDynamicSharedMemorySize,
                         SMEM_MMA);
    cudaFuncSetAttribute(k_scatter, cudaFuncAttributeMaxDynamicSharedMemorySize,
                         SC_SM_FLOATS * 4);

    k_prep<<<4, 256>>>(cb);
    k_cbhalf<<<256, 256>>>(cb);
    k_ztrans<<<512, 256, 256 * 65 * 4>>>(z);
    k_mma<<<512, 256, SMEM_MMA>>>();
    k_rescore<<<4096, 256>>>(z, cb, out);
    k_scatter<<<1024, 256, SC_SM_FLOATS * 4>>>(cb, out);
    k_loss<<<1, 1>>>(out);
}

// round 12
// speedup vs baseline: 2.3508x; 1.0559x over previous
#include <cuda_runtime.h>
#include <cuda_fp16.h>
#include <math_constants.h>

// ---------------------------------------------------------------------------
// VQ-VAE quantize — fp16 HMMA candidate GEMM + exact fp32 chain rescoring.
// R11 build (measured 216.3 us) + the R8-measured rescore (25.5 us):
// contiguous g_zt chains + hashed loss partials. Everything else identical.
// Output (f32): [ z_q_out : 8388608 ][ loss : 1 ][ idx : 32768 ]
// ---------------------------------------------------------------------------

#define N_VEC   32768
#define C_DIM   256
#define N_EMB   1024
#define Z_ELEMS 8388608
#define LOSS_OFF 8388608
#define IDX_OFF  8388609
#define MARGIN  1e-3f
#define CAP     24

__device__ float  g_e2[N_EMB];
__device__ float  g_rowA[N_VEC];
__device__ int    g_idx[N_VEC];
__device__ double g_loss_part[64];
__device__ float  g_zt[N_VEC * C_DIM];      // z transposed [n][k] fp32
__device__ __half g_zh[N_VEC * C_DIM];      // z transposed [n][k] fp16
__device__ __half g_ch[N_EMB * C_DIM];      // codebook fp16
__device__ unsigned short g_cand[N_VEC * CAP];
__device__ float  g_candd[N_VEC * CAP];
__device__ int    g_cnt[N_VEC];
__device__ float  g_bestd[N_VEC];

// ---------------- helpers ----------------
__device__ __forceinline__ unsigned su32(const void* p) {
    unsigned a;
    asm("{ .reg .u64 t; cvta.to.shared.u64 t, %1; cvt.u32.u64 %0, t; }"
        : "=r"(a) : "l"(p));
    return a;
}
__device__ __forceinline__ void cpa16(unsigned s, const void* g) {
    asm volatile("cp.async.cg.shared.global [%0], [%1], 16;"
                 :: "r"(s), "l"(g) : "memory");
}
#define CPA_COMMIT() asm volatile("cp.async.commit_group;" ::: "memory")
__device__ __forceinline__ void ldm4(unsigned* r, unsigned a) {
    asm volatile("ldmatrix.sync.aligned.m8n8.x4.shared.b16 {%0,%1,%2,%3}, [%4];"
                 : "=r"(r[0]), "=r"(r[1]), "=r"(r[2]), "=r"(r[3]) : "r"(a));
}
__device__ __forceinline__ void mma16816(float* c, const unsigned* a,
                                         const unsigned* b) {
    asm volatile(
        "mma.sync.aligned.m16n8k16.row.col.f32.f16.f16.f32 "
        "{%0,%1,%2,%3}, {%4,%5,%6,%7}, {%8,%9}, {%0,%1,%2,%3};"
        : "+f"(c[0]), "+f"(c[1]), "+f"(c[2]), "+f"(c[3])
        : "r"(a[0]), "r"(a[1]), "r"(a[2]), "r"(a[3]), "r"(b[0]), "r"(b[1]));
}
__device__ __forceinline__ unsigned fkey(float f) {
    unsigned b = __float_as_uint(f);
    return (b & 0x80000000u) ? ~b : (b | 0x80000000u);
}
__device__ __forceinline__ float funkey(unsigned k) {
    unsigned b = (k & 0x80000000u) ? (k & 0x7fffffffu) : ~k;
    return __uint_as_float(b);
}

// ---------------------------------------------------------------------------
// k_prep: exact B_e chains (reference order) + zero loss partials. grid 4x256.
// ---------------------------------------------------------------------------
__global__ void k_prep(const float* __restrict__ cb) {
    int e = blockIdx.x * 256 + threadIdx.x;
    if (e < 64) g_loss_part[e] = 0.0;
    const float* r = cb + e * C_DIM;
    float s = 0.f;
    for (int k = 0; k < C_DIM; ++k) {
        float v = r[k];
        s = __fadd_rn(s, __fmul_rn(v, v));
    }
    g_e2[e] = s;
}

// k_cbhalf: codebook fp32 -> fp16, coalesced. grid 256x256.
__global__ void k_cbhalf(const float* __restrict__ cb) {
    int i = blockIdx.x * 1024 + threadIdx.x;
    #pragma unroll
    for (int q = 0; q < 4; ++q) {
        int j = i + q * 256;
        g_ch[j] = __float2half_rn(cb[j]);
    }
}

// ---------------------------------------------------------------------------
// k_ztrans: transpose z -> fp16 + fp32 [n][k] + exact A_n chains. grid 512x256.
// ---------------------------------------------------------------------------
__global__ void k_ztrans(const float* __restrict__ z) {
    extern __shared__ float As[];                 // [256][65]
    const int tid = threadIdx.x;
    const int nb  = blockIdx.x;                   // (b,h)
    const int b   = nb >> 6, h = nb & 63;
    const float* zbase = z + ((long)b << 20) + h * 64;
    {
        const int w = tid & 63, c0 = tid >> 6;
        #pragma unroll 8
        for (int p = 0; p < 64; ++p) {
            int c = c0 + (p << 2);
            As[c * 65 + w] = zbase[(long)c << 12 | w];
        }
    }
    __syncthreads();
    #pragma unroll 4
    for (int w = 0; w < 64; ++w) {
        long row = (long)nb * 64 + w;
        float v = As[tid * 65 + w];
        g_zt[row * 256 + tid] = v;
        g_zh[row * 256 + tid] = __float2half_rn(v);
    }
    if (tid < 64) {
        float s = 0.f;
        for (int c = 0; c < C_DIM; ++c) {
            float v = As[c * 65 + tid];
            s = __fadd_rn(s, __fmul_rn(v, v));
        }
        g_rowA[nb * 64 + tid] = s;
    }
}

// ---------------------------------------------------------------------------
// k_mma: fp16 HMMA distance GEMM + fused running-min + candidate collection.
// (byte-identical to the R5/R11 kernel measured at 86.4-86.8 us)
// ---------------------------------------------------------------------------
#define MB 64
#define SMEM_MMA 82432

__device__ __forceinline__ void loadB(unsigned smB, int cc, int buf, int tid) {
    const int et = cc >> 2, kcw = cc & 3;
    #pragma unroll
    for (int q = 0; q < 4; ++q) {
        int i = q * 256 + tid;
        int n = (i >> 3) & 127, u = i & 7;
        unsigned s = smB + buf * 16384 + n * 128 + ((u ^ (n & 7)) << 4);
        cpa16(s, g_ch + ((long)(et * 128 + n) << 8) + kcw * 64 + u * 8);
    }
}

__global__ void __launch_bounds__(256, 2) k_mma() {
    extern __shared__ char sm[];
    const unsigned sb  = su32(sm);
    const unsigned smA = sb;
    const unsigned smB = sb + 32768;
    unsigned* skey = (unsigned*)(sm + 81920);
    int*      scnt = (int*)(sm + 82176);
    const int tid = threadIdx.x;
    const int n0  = blockIdx.x * MB;

    if (tid < MB) { skey[tid] = 0xFFFFFFFFu; scnt[tid] = 0; }

    #pragma unroll
    for (int q = 0; q < 8; ++q) {
        int i = q * 256 + tid;
        int kc = i >> 9, n = (i >> 3) & 63, u = i & 7;
        unsigned s = smA + kc * 8192 + n * 128 + ((u ^ (n & 7)) << 4);
        cpa16(s, g_zh + ((long)(n0 + n) << 8) + kc * 64 + u * 8);
    }
    loadB(smB, 0, 0, tid);
    CPA_COMMIT();
    loadB(smB, 1, 1, tid);
    CPA_COMMIT();

    const int lane = tid & 31, wid = tid >> 5;
    const int wm = wid >> 2, wn = wid & 3;
    const int quad = lane >> 2;

    unsigned aoff[2], axor[2], boff[2], bxor[2];
    #pragma unroll
    for (int fm = 0; fm < 2; ++fm) {
        int mr = wm * 32 + fm * 16 + (lane & 15);
        aoff[fm] = mr * 128;
        axor[fm] = (mr & 7) << 4;
    }
    #pragma unroll
    for (int nf = 0; nf < 2; ++nf) {
        int nr = wn * 32 + nf * 16 + (lane & 7) + ((lane >> 4) & 1) * 8;
        boff[nf] = nr * 128;
        bxor[nf] = (nr & 7) << 4;
    }
    const int akhi = (lane >> 4) * 16;
    const int bkhi = ((lane >> 3) & 1) * 16;

    float An[2][2];
    #pragma unroll
    for (int fm = 0; fm < 2; ++fm)
        #pragma unroll
        for (int h = 0; h < 2; ++h)
            An[fm][h] = g_rowA[n0 + wm * 32 + fm * 16 + quad + h * 8];

    float c[2][4][4];

    for (int cc = 0; cc < 32; ++cc) {
        if (cc >= 30) asm volatile("cp.async.wait_group 0;" ::: "memory");
        else          asm volatile("cp.async.wait_group 1;" ::: "memory");
        __syncthreads();
        if (cc + 2 < 32) {
            loadB(smB, cc + 2, (cc + 2) % 3, tid);
            CPA_COMMIT();
        }
        const int kcw = cc & 3, buf = cc % 3;
        if (kcw == 0) {
            #pragma unroll
            for (int fm = 0; fm < 2; ++fm)
                #pragma unroll
                for (int j = 0; j < 4; ++j)
                    #pragma unroll
                    for (int v = 0; v < 4; ++v) c[fm][j][v] = 0.f;
        }
        const unsigned Abase = smA + kcw * 8192;
        const unsigned Bbase = smB + buf * 16384;
        #pragma unroll
        for (int kk = 0; kk < 4; ++kk) {
            unsigned a[2][4], b[2][4];
            const int kb = kk * 32;
            #pragma unroll
            for (int fm = 0; fm < 2; ++fm)
                ldm4(a[fm], Abase + aoff[fm] + (unsigned)((kb + akhi) ^ axor[fm]));
            #pragma unroll
            for (int nf = 0; nf < 2; ++nf)
                ldm4(b[nf], Bbase + boff[nf] + (unsigned)((kb + bkhi) ^ bxor[nf]));
            #pragma unroll
            for (int fm = 0; fm < 2; ++fm) {
                mma16816(c[fm][0], a[fm], &b[0][0]);
                mma16816(c[fm][1], a[fm], &b[0][2]);
                mma16816(c[fm][2], a[fm], &b[1][0]);
                mma16816(c[fm][3], a[fm], &b[1][2]);
            }
        }
        if (kcw == 3) {
            const int et = cc >> 2;
            float Be[4][2];
            #pragma unroll
            for (int j = 0; j < 4; ++j) {
                int e0c = et * 128 + wn * 32 + j * 8 + (lane & 3) * 2;
                Be[j][0] = g_e2[e0c];
                Be[j][1] = g_e2[e0c + 1];
            }
            float dmin[2][2] = {{CUDART_INF_F, CUDART_INF_F},
                                {CUDART_INF_F, CUDART_INF_F}};
            #pragma unroll
            for (int fm = 0; fm < 2; ++fm)
                #pragma unroll
                for (int j = 0; j < 4; ++j)
                    #pragma unroll
                    for (int v = 0; v < 4; ++v) {
                        int h = v >> 1;
                        float d = fmaf(-2.f, c[fm][j][v], An[fm][h] + Be[j][v & 1]);
                        c[fm][j][v] = d;
                        dmin[fm][h] = fminf(dmin[fm][h], d);
                    }
            #pragma unroll
            for (int fm = 0; fm < 2; ++fm)
                #pragma unroll
                for (int h = 0; h < 2; ++h) {
                    float m = dmin[fm][h];
                    m = fminf(m, __shfl_xor_sync(0xFFFFFFFFu, m, 1));
                    m = fminf(m, __shfl_xor_sync(0xFFFFFFFFu, m, 2));
                    if ((lane & 3) == 0)
                        atomicMin(&skey[wm * 32 + fm * 16 + quad + h * 8], fkey(m));
                }
            __syncthreads();
            #pragma unroll
            for (int fm = 0; fm < 2; ++fm)
                #pragma unroll
                for (int j = 0; j < 4; ++j)
                    #pragma unroll
                    for (int v = 0; v < 4; ++v) {
                        int h = v >> 1;
                        int rloc = wm * 32 + fm * 16 + quad + h * 8;
                        float d = c[fm][j][v];
                        if (d <= funkey(skey[rloc]) + MARGIN) {
                            int slot = atomicAdd(&scnt[rloc], 1);
                            if (slot < CAP) {
                                int e = et * 128 + wn * 32 + j * 8
                                      + (lane & 3) * 2 + (v & 1);
                                g_cand[(long)(n0 + rloc) * CAP + slot] =
                                    (unsigned short)e;
                                g_candd[(long)(n0 + rloc) * CAP + slot] = d;
                            }
                        }
                    }
        }
    }
    __syncthreads();
    if (tid < MB) {
        g_bestd[n0 + tid] = funkey(skey[tid]);
        g_cnt[n0 + tid]   = scnt[tid];
    }
}

// ---------------------------------------------------------------------------
// k_rescore: R8-measured variant (25.5 us): contiguous g_zt chains + hashed
// loss partials. grid 4096 x 256 (warp per n).
// ---------------------------------------------------------------------------
__device__ __forceinline__ float chainM(const float4* __restrict__ zr,
                                        const float* __restrict__ cr) {
    float s = 0.f;
    #pragma unroll 16
    for (int q = 0; q < 64; ++q) {
        float4 a = __ldg(zr + q);
        float4 b = *(const float4*)(cr + q * 4);
        s = fmaf(a.x, b.x, s);
        s = fmaf(a.y, b.y, s);
        s = fmaf(a.z, b.z, s);
        s = fmaf(a.w, b.w, s);
    }
    return s;
}

__global__ void k_rescore(const float* __restrict__ cb,
                          float* __restrict__ out) {
    __shared__ double lsum[8];
    const int warp = threadIdx.x >> 5, lid = threadIdx.x & 31;
    const int n = blockIdx.x * 8 + warp;
    const int cnt = g_cnt[n];
    const float bmin = g_bestd[n];
    const float An = g_rowA[n];
    const float4* zr = (const float4*)(g_zt + (long)n * 256);

    float bd = CUDART_INF_F;
    int   bi = 0x7fffffff;

    if (cnt <= CAP) {
        float df = CUDART_INF_F;
        int   e  = 0x7fffffff;
        bool act = false;
        if (lid < cnt) {
            df = g_candd[(long)n * CAP + lid];
            e  = g_cand[(long)n * CAP + lid];
            act = (df <= bmin + MARGIN);
        }
        unsigned bal = __ballot_sync(0xFFFFFFFFu, act);
        if (__popc(bal) == 1) {
            if (act) { bd = df; bi = e; }       // provably the exact argmin
        } else if (act) {
            float M = chainM(zr, cb + (long)e * C_DIM);
            bd = __fsub_rn(__fadd_rn(An, g_e2[e]), __fmul_rn(2.0f, M));
            bi = e;
        }
    } else {
        for (int base = 0; base < N_EMB; base += 32) {
            int e = base + lid;
            float M = chainM(zr, cb + (long)e * C_DIM);
            float d = __fsub_rn(__fadd_rn(An, g_e2[e]), __fmul_rn(2.0f, M));
            if (d < bd || (d == bd && e < bi)) { bd = d; bi = e; }
        }
    }
    #pragma unroll
    for (int o = 16; o; o >>= 1) {
        float od = __shfl_xor_sync(0xFFFFFFFFu, bd, o);
        int   oi = __shfl_xor_sync(0xFFFFFFFFu, bi, o);
        if (od < bd || (od == bd && oi < bi)) { bd = od; bi = oi; }
    }
    if (lid == 0) {
        g_idx[n] = bi;
        out[IDX_OFF + n] = (float)bi;
        lsum[warp] = (double)bd;
    }
    __syncthreads();
    if (threadIdx.x == 0) {
        double s = 0.0;
        #pragma unroll
        for (int w = 0; w < 8; ++w) s += lsum[w];
        atomicAdd(&g_loss_part[blockIdx.x & 63], s);
    }
}

// ---------------------------------------------------------------------------
// k_scatter: grid 1024 (block = (b,h) x c-half), float4 writes (R11 proven).
// ---------------------------------------------------------------------------
#define SC_SM_FLOATS (128 * 68 + 64)
__global__ void k_scatter(const float* __restrict__ cb,
                          float* __restrict__ out)
{
    extern __shared__ float ss[];
    float* srow = ss;                         // [128][68]
    int*   sidx = (int*)(ss + 128 * 68);

    const int tid = threadIdx.x;
    const int nb = blockIdx.x >> 1, chalf = blockIdx.x & 1;
    if (tid < 64) sidx[tid] = g_idx[nb * 64 + tid];
    __syncthreads();

    #pragma unroll 8
    for (int it = 0; it < 32; ++it) {
        int i = it * 256 + tid;
        int w = i >> 7, cloc = i & 127;
        srow[cloc * 68 + w] = __ldg(&cb[sidx[w] * C_DIM + chalf * 128 + cloc]);
    }
    __syncthreads();

    const int b = nb >> 6, h = nb & 63;
    const int w4 = (tid & 15) << 2;
    float* base = out + ((long)b << 20) + ((long)chalf << 19) + (h << 6);
    #pragma unroll
    for (int p = 0; p < 8; ++p) {
        int cloc = (tid >> 4) + p * 16;
        *(float4*)&base[((long)cloc << 12) + w4] =
            *(float4*)&srow[cloc * 68 + w4];
    }
}

__global__ void k_loss(float* __restrict__ out) {
    double s = 0.0;
    #pragma unroll
    for (int i = 0; i < 64; ++i) s += g_loss_part[i];
    out[LOSS_OFF] = (float)(1.25 * s / (double)Z_ELEMS);
}

// ---------------------------------------------------------------------------
extern "C" void kernel_launch(void* const* d_in, const int* in_sizes, int n_in,
                              void* d_out, int out_size) {
    const float* z  = (const float*)d_in[0];
    const float* cb = (const float*)d_in[1];
    if (n_in >= 2 && in_sizes[0] == N_EMB * C_DIM && in_sizes[1] == Z_ELEMS) {
        z  = (const float*)d_in[1];
        cb = (const float*)d_in[0];
    }
    float* out = (float*)d_out;

    cudaFuncSetAttribute(k_ztrans, cudaFuncAttributeMaxDynamicSharedMemorySize,
                         256 * 65 * 4);
    cudaFuncSetAttribute(k_mma, cudaFuncAttributeMaxDynamicSharedMemorySize,
                         SMEM_MMA);
    cudaFuncSetAttribute(k_scatter, cudaFuncAttributeMaxDynamicSharedMemorySize,
                         SC_SM_FLOATS * 4);

    k_prep<<<4, 256>>>(cb);
    k_cbhalf<<<256, 256>>>(cb);
    k_ztrans<<<512, 256, 256 * 65 * 4>>>(z);
    k_mma<<<512, 256, SMEM_MMA>>>();
    k_rescore<<<4096, 256>>>(cb, out);
    k_scatter<<<1024, 256, SC_SM_FLOATS * 4>>>(cb, out);
    k_loss<<<1, 1>>>(out);
}

// round 14
// speedup vs baseline: 2.8323x; 1.2048x over previous
#include <cuda_runtime.h>
#include <cuda_fp16.h>
#include <math_constants.h>

// ---------------------------------------------------------------------------
// VQ-VAE quantize — fp16 HMMA candidate GEMM + exact fp32 chain rescoring.
// R12 build (measured 204.8 us) with ONE change: k_prep + k_cbhalf fused into
// k_prep2 (coalesced smem-staged codebook pass; e2 chains bit-identical).
// (Resubmission of R13 — previous round died in the GB300 container broker.)
// Output (f32): [ z_q_out : 8388608 ][ loss : 1 ][ idx : 32768 ]
// ---------------------------------------------------------------------------

#define N_VEC   32768
#define C_DIM   256
#define N_EMB   1024
#define Z_ELEMS 8388608
#define LOSS_OFF 8388608
#define IDX_OFF  8388609
#define MARGIN  1e-3f
#define CAP     24

__device__ float  g_e2[N_EMB];
__device__ float  g_rowA[N_VEC];
__device__ int    g_idx[N_VEC];
__device__ double g_loss_part[64];
__device__ float  g_zt[N_VEC * C_DIM];      // z transposed [n][k] fp32
__device__ __half g_zh[N_VEC * C_DIM];      // z transposed [n][k] fp16
__device__ __half g_ch[N_EMB * C_DIM];      // codebook fp16
__device__ unsigned short g_cand[N_VEC * CAP];
__device__ float  g_candd[N_VEC * CAP];
__device__ int    g_cnt[N_VEC];
__device__ float  g_bestd[N_VEC];

// ---------------- helpers ----------------
__device__ __forceinline__ unsigned su32(const void* p) {
    unsigned a;
    asm("{ .reg .u64 t; cvta.to.shared.u64 t, %1; cvt.u32.u64 %0, t; }"
        : "=r"(a) : "l"(p));
    return a;
}
__device__ __forceinline__ void cpa16(unsigned s, const void* g) {
    asm volatile("cp.async.cg.shared.global [%0], [%1], 16;"
                 :: "r"(s), "l"(g) : "memory");
}
#define CPA_COMMIT() asm volatile("cp.async.commit_group;" ::: "memory")
__device__ __forceinline__ void ldm4(unsigned* r, unsigned a) {
    asm volatile("ldmatrix.sync.aligned.m8n8.x4.shared.b16 {%0,%1,%2,%3}, [%4];"
                 : "=r"(r[0]), "=r"(r[1]), "=r"(r[2]), "=r"(r[3]) : "r"(a));
}
__device__ __forceinline__ void mma16816(float* c, const unsigned* a,
                                         const unsigned* b) {
    asm volatile(
        "mma.sync.aligned.m16n8k16.row.col.f32.f16.f16.f32 "
        "{%0,%1,%2,%3}, {%4,%5,%6,%7}, {%8,%9}, {%0,%1,%2,%3};"
        : "+f"(c[0]), "+f"(c[1]), "+f"(c[2]), "+f"(c[3])
        : "r"(a[0]), "r"(a[1]), "r"(a[2]), "r"(a[3]), "r"(b[0]), "r"(b[1]));
}
__device__ __forceinline__ unsigned fkey(float f) {
    unsigned b = __float_as_uint(f);
    return (b & 0x80000000u) ? ~b : (b | 0x80000000u);
}
__device__ __forceinline__ float funkey(unsigned k) {
    unsigned b = (k & 0x80000000u) ? (k & 0x7fffffffu) : ~k;
    return __uint_as_float(b);
}

// ---------------------------------------------------------------------------
// k_prep2: fused codebook pass. grid 128 x 256; block = 8 codebook rows.
// Coalesced loads -> smem (padded stride 257) + coalesced fp16 store; then
// 8 threads run the exact sequential e2 chains (reference order, bit-exact).
// ---------------------------------------------------------------------------
__global__ void k_prep2(const float* __restrict__ cb) {
    __shared__ float srow[8 * 257];
    const int tid = threadIdx.x;
    if (blockIdx.x == 0 && tid < 64) g_loss_part[tid] = 0.0;
    const int e0 = blockIdx.x * 8;
    #pragma unroll
    for (int it = 0; it < 8; ++it) {
        float v = __ldg(&cb[(e0 + it) * C_DIM + tid]);
        srow[it * 257 + tid] = v;
        g_ch[(e0 + it) * C_DIM + tid] = __float2half_rn(v);
    }
    __syncthreads();
    if (tid < 8) {
        float s = 0.f;
        for (int k = 0; k < C_DIM; ++k) {
            float v = srow[tid * 257 + k];
            s = __fadd_rn(s, __fmul_rn(v, v));
        }
        g_e2[e0 + tid] = s;
    }
}

// ---------------------------------------------------------------------------
// k_ztrans: transpose z -> fp16 + fp32 [n][k] + exact A_n chains. grid 512x256.
// ---------------------------------------------------------------------------
__global__ void k_ztrans(const float* __restrict__ z) {
    extern __shared__ float As[];                 // [256][65]
    const int tid = threadIdx.x;
    const int nb  = blockIdx.x;                   // (b,h)
    const int b   = nb >> 6, h = nb & 63;
    const float* zbase = z + ((long)b << 20) + h * 64;
    {
        const int w = tid & 63, c0 = tid >> 6;
        #pragma unroll 8
        for (int p = 0; p < 64; ++p) {
            int c = c0 + (p << 2);
            As[c * 65 + w] = zbase[(long)c << 12 | w];
        }
    }
    __syncthreads();
    #pragma unroll 4
    for (int w = 0; w < 64; ++w) {
        long row = (long)nb * 64 + w;
        float v = As[tid * 65 + w];
        g_zt[row * 256 + tid] = v;
        g_zh[row * 256 + tid] = __float2half_rn(v);
    }
    if (tid < 64) {
        float s = 0.f;
        for (int c = 0; c < C_DIM; ++c) {
            float v = As[c * 65 + tid];
            s = __fadd_rn(s, __fmul_rn(v, v));
        }
        g_rowA[nb * 64 + tid] = s;
    }
}

// ---------------------------------------------------------------------------
// k_mma: fp16 HMMA distance GEMM + fused running-min + candidate collection.
// (byte-identical to the R5/R11/R12 kernel measured at 86.4-86.8 us)
// ---------------------------------------------------------------------------
#define MB 64
#define SMEM_MMA 82432

__device__ __forceinline__ void loadB(unsigned smB, int cc, int buf, int tid) {
    const int et = cc >> 2, kcw = cc & 3;
    #pragma unroll
    for (int q = 0; q < 4; ++q) {
        int i = q * 256 + tid;
        int n = (i >> 3) & 127, u = i & 7;
        unsigned s = smB + buf * 16384 + n * 128 + ((u ^ (n & 7)) << 4);
        cpa16(s, g_ch + ((long)(et * 128 + n) << 8) + kcw * 64 + u * 8);
    }
}

__global__ void __launch_bounds__(256, 2) k_mma() {
    extern __shared__ char sm[];
    const unsigned sb  = su32(sm);
    const unsigned smA = sb;
    const unsigned smB = sb + 32768;
    unsigned* skey = (unsigned*)(sm + 81920);
    int*      scnt = (int*)(sm + 82176);
    const int tid = threadIdx.x;
    const int n0  = blockIdx.x * MB;

    if (tid < MB) { skey[tid] = 0xFFFFFFFFu; scnt[tid] = 0; }

    #pragma unroll
    for (int q = 0; q < 8; ++q) {
        int i = q * 256 + tid;
        int kc = i >> 9, n = (i >> 3) & 63, u = i & 7;
        unsigned s = smA + kc * 8192 + n * 128 + ((u ^ (n & 7)) << 4);
        cpa16(s, g_zh + ((long)(n0 + n) << 8) + kc * 64 + u * 8);
    }
    loadB(smB, 0, 0, tid);
    CPA_COMMIT();
    loadB(smB, 1, 1, tid);
    CPA_COMMIT();

    const int lane = tid & 31, wid = tid >> 5;
    const int wm = wid >> 2, wn = wid & 3;
    const int quad = lane >> 2;

    unsigned aoff[2], axor[2], boff[2], bxor[2];
    #pragma unroll
    for (int fm = 0; fm < 2; ++fm) {
        int mr = wm * 32 + fm * 16 + (lane & 15);
        aoff[fm] = mr * 128;
        axor[fm] = (mr & 7) << 4;
    }
    #pragma unroll
    for (int nf = 0; nf < 2; ++nf) {
        int nr = wn * 32 + nf * 16 + (lane & 7) + ((lane >> 4) & 1) * 8;
        boff[nf] = nr * 128;
        bxor[nf] = (nr & 7) << 4;
    }
    const int akhi = (lane >> 4) * 16;
    const int bkhi = ((lane >> 3) & 1) * 16;

    float An[2][2];
    #pragma unroll
    for (int fm = 0; fm < 2; ++fm)
        #pragma unroll
        for (int h = 0; h < 2; ++h)
            An[fm][h] = g_rowA[n0 + wm * 32 + fm * 16 + quad + h * 8];

    float c[2][4][4];

    for (int cc = 0; cc < 32; ++cc) {
        if (cc >= 30) asm volatile("cp.async.wait_group 0;" ::: "memory");
        else          asm volatile("cp.async.wait_group 1;" ::: "memory");
        __syncthreads();
        if (cc + 2 < 32) {
            loadB(smB, cc + 2, (cc + 2) % 3, tid);
            CPA_COMMIT();
        }
        const int kcw = cc & 3, buf = cc % 3;
        if (kcw == 0) {
            #pragma unroll
            for (int fm = 0; fm < 2; ++fm)
                #pragma unroll
                for (int j = 0; j < 4; ++j)
                    #pragma unroll
                    for (int v = 0; v < 4; ++v) c[fm][j][v] = 0.f;
        }
        const unsigned Abase = smA + kcw * 8192;
        const unsigned Bbase = smB + buf * 16384;
        #pragma unroll
        for (int kk = 0; kk < 4; ++kk) {
            unsigned a[2][4], b[2][4];
            const int kb = kk * 32;
            #pragma unroll
            for (int fm = 0; fm < 2; ++fm)
                ldm4(a[fm], Abase + aoff[fm] + (unsigned)((kb + akhi) ^ axor[fm]));
            #pragma unroll
            for (int nf = 0; nf < 2; ++nf)
                ldm4(b[nf], Bbase + boff[nf] + (unsigned)((kb + bkhi) ^ bxor[nf]));
            #pragma unroll
            for (int fm = 0; fm < 2; ++fm) {
                mma16816(c[fm][0], a[fm], &b[0][0]);
                mma16816(c[fm][1], a[fm], &b[0][2]);
                mma16816(c[fm][2], a[fm], &b[1][0]);
                mma16816(c[fm][3], a[fm], &b[1][2]);
            }
        }
        if (kcw == 3) {
            const int et = cc >> 2;
            float Be[4][2];
            #pragma unroll
            for (int j = 0; j < 4; ++j) {
                int e0c = et * 128 + wn * 32 + j * 8 + (lane & 3) * 2;
                Be[j][0] = g_e2[e0c];
                Be[j][1] = g_e2[e0c + 1];
            }
            float dmin[2][2] = {{CUDART_INF_F, CUDART_INF_F},
                                {CUDART_INF_F, CUDART_INF_F}};
            #pragma unroll
            for (int fm = 0; fm < 2; ++fm)
                #pragma unroll
                for (int j = 0; j < 4; ++j)
                    #pragma unroll
                    for (int v = 0; v < 4; ++v) {
                        int h = v >> 1;
                        float d = fmaf(-2.f, c[fm][j][v], An[fm][h] + Be[j][v & 1]);
                        c[fm][j][v] = d;
                        dmin[fm][h] = fminf(dmin[fm][h], d);
                    }
            #pragma unroll
            for (int fm = 0; fm < 2; ++fm)
                #pragma unroll
                for (int h = 0; h < 2; ++h) {
                    float m = dmin[fm][h];
                    m = fminf(m, __shfl_xor_sync(0xFFFFFFFFu, m, 1));
                    m = fminf(m, __shfl_xor_sync(0xFFFFFFFFu, m, 2));
                    if ((lane & 3) == 0)
                        atomicMin(&skey[wm * 32 + fm * 16 + quad + h * 8], fkey(m));
                }
            __syncthreads();
            #pragma unroll
            for (int fm = 0; fm < 2; ++fm)
                #pragma unroll
                for (int j = 0; j < 4; ++j)
                    #pragma unroll
                    for (int v = 0; v < 4; ++v) {
                        int h = v >> 1;
                        int rloc = wm * 32 + fm * 16 + quad + h * 8;
                        float d = c[fm][j][v];
                        if (d <= funkey(skey[rloc]) + MARGIN) {
                            int slot = atomicAdd(&scnt[rloc], 1);
                            if (slot < CAP) {
                                int e = et * 128 + wn * 32 + j * 8
                                      + (lane & 3) * 2 + (v & 1);
                                g_cand[(long)(n0 + rloc) * CAP + slot] =
                                    (unsigned short)e;
                                g_candd[(long)(n0 + rloc) * CAP + slot] = d;
                            }
                        }
                    }
        }
    }
    __syncthreads();
    if (tid < MB) {
        g_bestd[n0 + tid] = funkey(skey[tid]);
        g_cnt[n0 + tid]   = scnt[tid];
    }
}

// ---------------------------------------------------------------------------
// k_rescore: R12-proven (contiguous g_zt chains + hashed loss partials).
// grid 4096 x 256 (warp per n).
// ---------------------------------------------------------------------------
__device__ __forceinline__ float chainM(const float4* __restrict__ zr,
                                        const float* __restrict__ cr) {
    float s = 0.f;
    #pragma unroll 16
    for (int q = 0; q < 64; ++q) {
        float4 a = __ldg(zr + q);
        float4 b = *(const float4*)(cr + q * 4);
        s = fmaf(a.x, b.x, s);
        s = fmaf(a.y, b.y, s);
        s = fmaf(a.z, b.z, s);
        s = fmaf(a.w, b.w, s);
    }
    return s;
}

__global__ void k_rescore(const float* __restrict__ cb,
                          float* __restrict__ out) {
    __shared__ double lsum[8];
    const int warp = threadIdx.x >> 5, lid = threadIdx.x & 31;
    const int n = blockIdx.x * 8 + warp;
    const int cnt = g_cnt[n];
    const float bmin = g_bestd[n];
    const float An = g_rowA[n];
    const float4* zr = (const float4*)(g_zt + (long)n * 256);

    float bd = CUDART_INF_F;
    int   bi = 0x7fffffff;

    if (cnt <= CAP) {
        float df = CUDART_INF_F;
        int   e  = 0x7fffffff;
        bool act = false;
        if (lid < cnt) {
            df = g_candd[(long)n * CAP + lid];
            e  = g_cand[(long)n * CAP + lid];
            act = (df <= bmin + MARGIN);
        }
        unsigned bal = __ballot_sync(0xFFFFFFFFu, act);
        if (__popc(bal) == 1) {
            if (act) { bd = df; bi = e; }       // provably the exact argmin
        } else if (act) {
            float M = chainM(zr, cb + (long)e * C_DIM);
            bd = __fsub_rn(__fadd_rn(An, g_e2[e]), __fmul_rn(2.0f, M));
            bi = e;
        }
    } else {
        for (int base = 0; base < N_EMB; base += 32) {
            int e = base + lid;
            float M = chainM(zr, cb + (long)e * C_DIM);
            float d = __fsub_rn(__fadd_rn(An, g_e2[e]), __fmul_rn(2.0f, M));
            if (d < bd || (d == bd && e < bi)) { bd = d; bi = e; }
        }
    }
    #pragma unroll
    for (int o = 16; o; o >>= 1) {
        float od = __shfl_xor_sync(0xFFFFFFFFu, bd, o);
        int   oi = __shfl_xor_sync(0xFFFFFFFFu, bi, o);
        if (od < bd || (od == bd && oi < bi)) { bd = od; bi = oi; }
    }
    if (lid == 0) {
        g_idx[n] = bi;
        out[IDX_OFF + n] = (float)bi;
        lsum[warp] = (double)bd;
    }
    __syncthreads();
    if (threadIdx.x == 0) {
        double s = 0.0;
        #pragma unroll
        for (int w = 0; w < 8; ++w) s += lsum[w];
        atomicAdd(&g_loss_part[blockIdx.x & 63], s);
    }
}

// ---------------------------------------------------------------------------
// k_scatter: grid 1024 (block = (b,h) x c-half), float4 writes (proven).
// ---------------------------------------------------------------------------
#define SC_SM_FLOATS (128 * 68 + 64)
__global__ void k_scatter(const float* __restrict__ cb,
                          float* __restrict__ out)
{
    extern __shared__ float ss[];
    float* srow = ss;                         // [128][68]
    int*   sidx = (int*)(ss + 128 * 68);

    const int tid = threadIdx.x;
    const int nb = blockIdx.x >> 1, chalf = blockIdx.x & 1;
    if (tid < 64) sidx[tid] = g_idx[nb * 64 + tid];
    __syncthreads();

    #pragma unroll 8
    for (int it = 0; it < 32; ++it) {
        int i = it * 256 + tid;
        int w = i >> 7, cloc = i & 127;
        srow[cloc * 68 + w] = __ldg(&cb[sidx[w] * C_DIM + chalf * 128 + cloc]);
    }
    __syncthreads();

    const int b = nb >> 6, h = nb & 63;
    const int w4 = (tid & 15) << 2;
    float* base = out + ((long)b << 20) + ((long)chalf << 19) + (h << 6);
    #pragma unroll
    for (int p = 0; p < 8; ++p) {
        int cloc = (tid >> 4) + p * 16;
        *(float4*)&base[((long)cloc << 12) + w4] =
            *(float4*)&srow[cloc * 68 + w4];
    }
}

__global__ void k_loss(float* __restrict__ out) {
    double s = 0.0;
    #pragma unroll
    for (int i = 0; i < 64; ++i) s += g_loss_part[i];
    out[LOSS_OFF] = (float)(1.25 * s / (double)Z_ELEMS);
}

// ---------------------------------------------------------------------------
extern "C" void kernel_launch(void* const* d_in, const int* in_sizes, int n_in,
                              void* d_out, int out_size) {
    const float* z  = (const float*)d_in[0];
    const float* cb = (const float*)d_in[1];
    if (n_in >= 2 && in_sizes[0] == N_EMB * C_DIM && in_sizes[1] == Z_ELEMS) {
        z  = (const float*)d_in[1];
        cb = (const float*)d_in[0];
    }
    float* out = (float*)d_out;

    cudaFuncSetAttribute(k_ztrans, cudaFuncAttributeMaxDynamicSharedMemorySize,
                         256 * 65 * 4);
    cudaFuncSetAttribute(k_mma, cudaFuncAttributeMaxDynamicSharedMemorySize,
                         SMEM_MMA);
    cudaFuncSetAttribute(k_scatter, cudaFuncAttributeMaxDynamicSharedMemorySize,
                         SC_SM_FLOATS * 4);

    k_prep2<<<128, 256>>>(cb);
    k_ztrans<<<512, 256, 256 * 65 * 4>>>(z);
    k_mma<<<512, 256, SMEM_MMA>>>();
    k_rescore<<<4096, 256>>>(cb, out);
    k_scatter<<<1024, 256, SC_SM_FLOATS * 4>>>(cb, out);
    k_loss<<<1, 1>>>(out);
}